// round 15
// baseline (speedup 1.0000x reference)
#include <cuda_runtime.h>
#include <cuda_fp16.h>

// VecInt: 7-step scaling-and-squaring integration of [2,128,128,128,3] f32.
//   v0 = vel/128;  v <- v + trilinear_warp(v, v)  x7
//
// R15 = R11 mid passes (fp16x4 voxels, single-copy ping-pong, adjacent-d
// voxel pair per thread, interleaved front-loaded 2x9 LDG.64 burst,
// __ldcs/__stcs hints, 256-thr CTAs, 32 regs) + a smem-staged final pass:
// the packed-f32 output (6 floats/thread at 12B stride = 3 wavefronts per
// store instr) is staged in 6KB of smem and written as fully-coalesced
// uint4 streaming stores (1 wavefront each).
// Arithmetic identical to R7-R14 (rel_err 4.6838e-4).

static constexpr int DIMS = 128;
static constexpr int NB   = 2;
static constexpr int NVOX = NB * DIMS * DIMS * DIMS;
static constexpr int DSTRIDE = DIMS * DIMS;           // 16384

// +2 pad: zero-weighted stray read at iw0==127 lands here (zero-init'd).
__device__ __align__(16) uint2 g_bufA[NVOX + 2];
__device__ __align__(16) uint2 g_bufB[NVOX + 2];

__device__ __forceinline__ void h4_to_f3(uint2 u, float& x, float& y, float& z)
{
    __half2 h01 = *reinterpret_cast<__half2*>(&u.x);
    __half2 h23 = *reinterpret_cast<__half2*>(&u.y);
    float2  f01 = __half22float2(h01);
    x = f01.x; y = f01.y; z = __low2float(h23);
}

__device__ __forceinline__ uint2 f3_to_h4(float x, float y, float z)
{
    __half2 h01 = __floats2half2_rn(x, y);
    __half2 h23 = __floats2half2_rn(z, 0.0f);
    uint2 u;
    u.x = *reinterpret_cast<unsigned int*>(&h01);
    u.y = *reinterpret_cast<unsigned int*>(&h23);
    return u;
}

// ---------- pass 0: packed f32x3 -> fp16x4, folding 1/128 -------------------
__global__ __launch_bounds__(256)
void vecint_convert(const float4* __restrict__ in, uint4* __restrict__ out)
{
    const int t = blockIdx.x * blockDim.x + threadIdx.x;
    const float s = 1.0f / 128.0f;
    const float4 a = __ldcs(in + 3 * t + 0);   // read-once: evict-first
    const float4 b = __ldcs(in + 3 * t + 1);
    const float4 c = __ldcs(in + 3 * t + 2);
    const uint2 v0 = f3_to_h4(a.x * s, a.y * s, a.z * s);
    const uint2 v1 = f3_to_h4(a.w * s, b.x * s, b.y * s);
    const uint2 v2 = f3_to_h4(b.z * s, b.w * s, c.x * s);
    const uint2 v3 = f3_to_h4(c.y * s, c.z * s, c.w * s);
    out[2 * t + 0] = make_uint4(v0.x, v0.y, v1.x, v1.y);
    out[2 * t + 1] = make_uint4(v2.x, v2.y, v3.x, v3.y);
}

// ---------- per-voxel machinery ---------------------------------------------
struct Vx {
    int   r00, r01, r10, r11;
    float f0, f1, f2, w00, w01, w10, w11, ww0, ww1;
};

__device__ __forceinline__ Vx vx_setup(uint2 own, int b, float df, float hf,
                                       float wf)
{
    Vx v;
    h4_to_f3(own, v.f0, v.f1, v.f2);

    const float ldc = fminf(fmaxf(df + v.f0, 0.0f), 127.0f);
    const float lhc = fminf(fmaxf(hf + v.f1, 0.0f), 127.0f);
    const float lwc = fminf(fmaxf(wf + v.f2, 0.0f), 127.0f);

    const float fd = floorf(ldc), fh = floorf(lhc), fw = floorf(lwc);
    const int   id0 = (int)fd,  ih0 = (int)fh,  iw0 = (int)fw;
    const float wd1 = ldc - fd, wh1 = lhc - fh;
    const float wd0 = 1.0f - wd1, wh0 = 1.0f - wh1;
    v.ww1 = lwc - fw; v.ww0 = 1.0f - v.ww1;

    const int dd = (id0 < 127) ? DSTRIDE : 0;
    const int dh = (ih0 < 127) ? DIMS : 0;
    v.r00 = ((b * DIMS + id0) * DIMS + ih0) * DIMS + iw0;
    v.r01 = v.r00 + dh;
    v.r10 = v.r00 + dd;
    v.r11 = v.r10 + dh;

    v.w00 = wd0 * wh0; v.w01 = wd0 * wh1;
    v.w10 = wd1 * wh0; v.w11 = wd1 * wh1;
    return v;
}

struct Gather { uint2 a0, b0, a1, b1, a2, b2, a3, b3; };

__device__ __forceinline__ Gather vx_load(const uint2* __restrict__ in_v,
                                          const Vx& v)
{
    Gather g;
    g.a0 = in_v[v.r00]; g.b0 = in_v[v.r00 + 1];
    g.a1 = in_v[v.r01]; g.b1 = in_v[v.r01 + 1];
    g.a2 = in_v[v.r10]; g.b2 = in_v[v.r10 + 1];
    g.a3 = in_v[v.r11]; g.b3 = in_v[v.r11 + 1];
    return g;
}

__device__ __forceinline__ void vx_blend(const Vx& v, const Gather& g,
                                         float& o0, float& o1, float& o2)
{
    float r0 = 0.0f, r1 = 0.0f, r2 = 0.0f;
    float x0, y0, z0, x1, y1, z1;
#define BLEND(A, B, WDH)                                                  \
    h4_to_f3(A, x0, y0, z0); h4_to_f3(B, x1, y1, z1);                     \
    {   const float g0 = (WDH) * v.ww0, g1 = (WDH) * v.ww1;               \
        r0 = fmaf(g0, x0, fmaf(g1, x1, r0));                              \
        r1 = fmaf(g0, y0, fmaf(g1, y1, r1));                              \
        r2 = fmaf(g0, z0, fmaf(g1, z1, r2)); }
    BLEND(g.a0, g.b0, v.w00)
    BLEND(g.a1, g.b1, v.w01)
    BLEND(g.a2, g.b2, v.w10)
    BLEND(g.a3, g.b3, v.w11)
#undef BLEND
    o0 = v.f0 + r0; o1 = v.f1 + r1; o2 = v.f2 + r2;
}

// ---------- mid step: adjacent-d voxel pair per thread (R11 exact) ----------
__global__ __launch_bounds__(256)
void vecint_step_mid(const uint2* __restrict__ in_v,
                     uint2*       __restrict__ out_v)
{
    const int w  = blockIdx.x * 32 + threadIdx.x;
    const int h  = blockIdx.y * 4  + threadIdx.y;
    const int zb = blockIdx.z;                  // 64: 32 d-quads x 2 batches
    const int b  = zb >> 5;
    const int d  = ((zb & 31) << 2) + (threadIdx.z << 1);  // pair: d, d+1

    const int baseA = ((b * DIMS + d) * DIMS + h) * DIMS + w;
    const int baseB = baseA + DSTRIDE;

    const uint2 ownA = in_v[baseA];
    const uint2 ownB = in_v[baseB];

    const float hf = (float)h, wf = (float)w, df = (float)d;

    const Vx vA = vx_setup(ownA, b, df,        hf, wf);
    const Vx vB = vx_setup(ownB, b, df + 1.0f, hf, wf);

    // Interleaved front-loaded gather bursts (~16 loads in flight).
    Gather gA, gB;
    gA.a0 = in_v[vA.r00];     gB.a0 = in_v[vB.r00];
    gA.b0 = in_v[vA.r00 + 1]; gB.b0 = in_v[vB.r00 + 1];
    gA.a1 = in_v[vA.r01];     gB.a1 = in_v[vB.r01];
    gA.b1 = in_v[vA.r01 + 1]; gB.b1 = in_v[vB.r01 + 1];
    gA.a2 = in_v[vA.r10];     gB.a2 = in_v[vB.r10];
    gA.b2 = in_v[vA.r10 + 1]; gB.b2 = in_v[vB.r10 + 1];
    gA.a3 = in_v[vA.r11];     gB.a3 = in_v[vB.r11];
    gA.b3 = in_v[vA.r11 + 1]; gB.b3 = in_v[vB.r11 + 1];

    float a0, a1, a2, b0, b1, b2;
    vx_blend(vA, gA, a0, a1, a2);
    vx_blend(vB, gB, b0, b1, b2);

    out_v[baseA] = f3_to_h4(a0, a1, a2);
    out_v[baseB] = f3_to_h4(b0, b1, b2);
}

// ---------- final step: gather + smem-staged coalesced packed stores --------
__global__ __launch_bounds__(256)
void vecint_step_final(const uint2* __restrict__ in_v,
                       float*       __restrict__ out_p)
{
    // Block covers 4 d x 4 h x 32 w voxels; packed output = 6144B staged here.
    __shared__ float sout[1536];

    const int tx = threadIdx.x, ty = threadIdx.y, tz = threadIdx.z;
    const int w  = blockIdx.x * 32 + tx;
    const int h0 = blockIdx.y * 4;
    const int h  = h0 + ty;
    const int zb = blockIdx.z;
    const int b  = zb >> 5;
    const int d0 = (zb & 31) << 2;
    const int d  = d0 + (tz << 1);              // pair: d, d+1

    const int baseA = ((b * DIMS + d) * DIMS + h) * DIMS + w;
    const int baseB = baseA + DSTRIDE;

    const uint2 ownA = in_v[baseA];
    const uint2 ownB = in_v[baseB];

    const float hf = (float)h, wf = (float)w, df = (float)d;

    const Vx vA = vx_setup(ownA, b, df,        hf, wf);
    const Vx vB = vx_setup(ownB, b, df + 1.0f, hf, wf);

    Gather gA, gB;
    gA.a0 = in_v[vA.r00];     gB.a0 = in_v[vB.r00];
    gA.b0 = in_v[vA.r00 + 1]; gB.b0 = in_v[vB.r00 + 1];
    gA.a1 = in_v[vA.r01];     gB.a1 = in_v[vB.r01];
    gA.b1 = in_v[vA.r01 + 1]; gB.b1 = in_v[vB.r01 + 1];
    gA.a2 = in_v[vA.r10];     gB.a2 = in_v[vB.r10];
    gA.b2 = in_v[vA.r10 + 1]; gB.b2 = in_v[vB.r10 + 1];
    gA.a3 = in_v[vA.r11];     gB.a3 = in_v[vB.r11];
    gA.b3 = in_v[vA.r11 + 1]; gB.b3 = in_v[vB.r11 + 1];

    float a0, a1, a2, b0, b1, b2;
    vx_blend(vA, gA, a0, a1, a2);
    vx_blend(vB, gB, b0, b1, b2);

    // Stage packed values: local row lr = d_local*4 + ty, lr in [0,16).
    // smem float offset = (lr*32 + tx)*3 + c  (stride-3 writes: conflict-free)
    {
        const int lrA = ((tz << 1) + 0) * 4 + ty;
        const int lrB = ((tz << 1) + 1) * 4 + ty;
        float* pA = sout + (lrA * 32 + tx) * 3;
        pA[0] = a0; pA[1] = a1; pA[2] = a2;
        float* pB = sout + (lrB * 32 + tx) * 3;
        pB[0] = b0; pB[1] = b1; pB[2] = b2;
    }
    __syncthreads();

    // Coalesced store: 384 uint4 (16 rows x 24 uint4). Each row's 384B global
    // segment is 16B-aligned (base divisible by 32 -> base*12B % 128 == 0).
    const int tid = (tz * 4 + ty) * 32 + tx;
    const uint4* su4 = reinterpret_cast<const uint4*>(sout);
#pragma unroll
    for (int i = tid; i < 384; i += 256) {
        const int r = i / 24;                  // local row 0..15
        const int j = i % 24;                  // uint4 within row
        const int gr = ((b * DIMS + d0 + (r >> 2)) * DIMS + h0 + (r & 3))
                       * DIMS + blockIdx.x * 32;           // global voxel base
        uint4* dst = reinterpret_cast<uint4*>(out_p + (size_t)gr * 3) + j;
        __stcs(dst, su4[r * 24 + j]);
    }
}

extern "C" void kernel_launch(void* const* d_in, const int* in_sizes, int n_in,
                              void* d_out, int out_size)
{
    (void)in_sizes; (void)n_in; (void)out_size;
    const float4* vel = (const float4*)d_in[0];
    float*        out = (float*)d_out;

    uint2 *A = nullptr, *B = nullptr;
    cudaGetSymbolAddress((void**)&A, g_bufA);
    cudaGetSymbolAddress((void**)&B, g_bufB);

    vecint_convert<<<NVOX / 4 / 256, 256>>>(vel, (uint4*)A);

    const dim3 blk(32, 4, 2);                               // 256 threads
    const dim3 grd(DIMS / 32, DIMS / 4, (DIMS / 4) * NB);   // 2 voxels/thread

    vecint_step_mid<<<grd, blk>>>(A, B);    // 1
    vecint_step_mid<<<grd, blk>>>(B, A);    // 2
    vecint_step_mid<<<grd, blk>>>(A, B);    // 3
    vecint_step_mid<<<grd, blk>>>(B, A);    // 4
    vecint_step_mid<<<grd, blk>>>(A, B);    // 5
    vecint_step_mid<<<grd, blk>>>(B, A);    // 6
    vecint_step_final<<<grd, blk>>>(A, out); // 7
}

// round 16
// speedup vs baseline: 1.0213x; 1.0213x over previous
#include <cuda_runtime.h>
#include <cuda_fp16.h>

// VecInt: 7-step scaling-and-squaring integration of [2,128,128,128,3] f32.
//   v0 = vel/128;  v <- v + trilinear_warp(v, v)  x7
//
// FINAL (= R11, the measured optimum at 178.2us):
//  - fp16x4 voxel storage (uint2), single-copy ping-pong buffers: 67MB live
//    set, L2-resident (every larger-footprint variant thrashed L2).
//  - 8x LDG.64 scattered gather per voxel — measured L1-wavefront optimum
//    (smem staging, dual-copy pair loads, chunk tricks all regressed).
//  - 2 adjacent-d voxels per thread, interleaved front-loaded gather bursts
//    (~18 loads in flight) to hide L2 return latency; 32 regs, ~83% occ.
//  - __ldcs on the read-once convert input; __stcs on the never-re-read
//    final output.
// rel_err 4.6838e-4 (fp16 storage of intermediates; all math in f32).

static constexpr int DIMS = 128;
static constexpr int NB   = 2;
static constexpr int NVOX = NB * DIMS * DIMS * DIMS;
static constexpr int DSTRIDE = DIMS * DIMS;           // 16384

// +2 pad: zero-weighted stray read at iw0==127 lands here (zero-init'd).
__device__ __align__(16) uint2 g_bufA[NVOX + 2];
__device__ __align__(16) uint2 g_bufB[NVOX + 2];

__device__ __forceinline__ void h4_to_f3(uint2 u, float& x, float& y, float& z)
{
    __half2 h01 = *reinterpret_cast<__half2*>(&u.x);
    __half2 h23 = *reinterpret_cast<__half2*>(&u.y);
    float2  f01 = __half22float2(h01);
    x = f01.x; y = f01.y; z = __low2float(h23);
}

__device__ __forceinline__ uint2 f3_to_h4(float x, float y, float z)
{
    __half2 h01 = __floats2half2_rn(x, y);
    __half2 h23 = __floats2half2_rn(z, 0.0f);
    uint2 u;
    u.x = *reinterpret_cast<unsigned int*>(&h01);
    u.y = *reinterpret_cast<unsigned int*>(&h23);
    return u;
}

// ---------- pass 0: packed f32x3 -> fp16x4, folding 1/128 -------------------
__global__ __launch_bounds__(256)
void vecint_convert(const float4* __restrict__ in, uint4* __restrict__ out)
{
    const int t = blockIdx.x * blockDim.x + threadIdx.x;
    const float s = 1.0f / 128.0f;
    const float4 a = __ldcs(in + 3 * t + 0);   // read-once: evict-first
    const float4 b = __ldcs(in + 3 * t + 1);
    const float4 c = __ldcs(in + 3 * t + 2);
    const uint2 v0 = f3_to_h4(a.x * s, a.y * s, a.z * s);
    const uint2 v1 = f3_to_h4(a.w * s, b.x * s, b.y * s);
    const uint2 v2 = f3_to_h4(b.z * s, b.w * s, c.x * s);
    const uint2 v3 = f3_to_h4(c.y * s, c.z * s, c.w * s);
    out[2 * t + 0] = make_uint4(v0.x, v0.y, v1.x, v1.y);
    out[2 * t + 1] = make_uint4(v2.x, v2.y, v3.x, v3.y);
}

// ---------- per-voxel machinery ---------------------------------------------
struct Vx {
    int   r00, r01, r10, r11;
    float f0, f1, f2, w00, w01, w10, w11, ww0, ww1;
};

__device__ __forceinline__ Vx vx_setup(uint2 own, int b, float df, float hf,
                                       float wf)
{
    Vx v;
    h4_to_f3(own, v.f0, v.f1, v.f2);

    const float ldc = fminf(fmaxf(df + v.f0, 0.0f), 127.0f);
    const float lhc = fminf(fmaxf(hf + v.f1, 0.0f), 127.0f);
    const float lwc = fminf(fmaxf(wf + v.f2, 0.0f), 127.0f);

    const float fd = floorf(ldc), fh = floorf(lhc), fw = floorf(lwc);
    const int   id0 = (int)fd,  ih0 = (int)fh,  iw0 = (int)fw;
    const float wd1 = ldc - fd, wh1 = lhc - fh;
    const float wd0 = 1.0f - wd1, wh0 = 1.0f - wh1;
    v.ww1 = lwc - fw; v.ww0 = 1.0f - v.ww1;

    const int dd = (id0 < 127) ? DSTRIDE : 0;
    const int dh = (ih0 < 127) ? DIMS : 0;
    v.r00 = ((b * DIMS + id0) * DIMS + ih0) * DIMS + iw0;
    v.r01 = v.r00 + dh;
    v.r10 = v.r00 + dd;
    v.r11 = v.r10 + dh;

    v.w00 = wd0 * wh0; v.w01 = wd0 * wh1;
    v.w10 = wd1 * wh0; v.w11 = wd1 * wh1;
    return v;
}

struct Gather { uint2 a0, b0, a1, b1, a2, b2, a3, b3; };

__device__ __forceinline__ void vx_blend(const Vx& v, const Gather& g,
                                         float& o0, float& o1, float& o2)
{
    float r0 = 0.0f, r1 = 0.0f, r2 = 0.0f;
    float x0, y0, z0, x1, y1, z1;
#define BLEND(A, B, WDH)                                                  \
    h4_to_f3(A, x0, y0, z0); h4_to_f3(B, x1, y1, z1);                     \
    {   const float g0 = (WDH) * v.ww0, g1 = (WDH) * v.ww1;               \
        r0 = fmaf(g0, x0, fmaf(g1, x1, r0));                              \
        r1 = fmaf(g0, y0, fmaf(g1, y1, r1));                              \
        r2 = fmaf(g0, z0, fmaf(g1, z1, r2)); }
    BLEND(g.a0, g.b0, v.w00)
    BLEND(g.a1, g.b1, v.w01)
    BLEND(g.a2, g.b2, v.w10)
    BLEND(g.a3, g.b3, v.w11)
#undef BLEND
    o0 = v.f0 + r0; o1 = v.f1 + r1; o2 = v.f2 + r2;
}

// ---------- integration step: adjacent-d voxel pair per thread --------------
template<bool OUT_PACKED>
__global__ __launch_bounds__(256)
void vecint_step(const uint2* __restrict__ in_v,
                 float*       __restrict__ out_p,
                 uint2*       __restrict__ out_v)
{
    const int w  = blockIdx.x * 32 + threadIdx.x;
    const int h  = blockIdx.y * 4  + threadIdx.y;
    const int zb = blockIdx.z;                  // 64: 32 d-quads x 2 batches
    const int b  = zb >> 5;
    const int d  = ((zb & 31) << 2) + (threadIdx.z << 1);  // pair: d, d+1

    const int baseA = ((b * DIMS + d) * DIMS + h) * DIMS + w;
    const int baseB = baseA + DSTRIDE;

    // Own-voxel loads first (both in flight).
    const uint2 ownA = in_v[baseA];
    const uint2 ownB = in_v[baseB];

    const float hf = (float)h, wf = (float)w, df = (float)d;

    const Vx vA = vx_setup(ownA, b, df,        hf, wf);
    const Vx vB = vx_setup(ownB, b, df + 1.0f, hf, wf);

    // Interleaved front-loaded gather bursts (~16 loads in flight).
    Gather gA, gB;
    gA.a0 = in_v[vA.r00];     gB.a0 = in_v[vB.r00];
    gA.b0 = in_v[vA.r00 + 1]; gB.b0 = in_v[vB.r00 + 1];
    gA.a1 = in_v[vA.r01];     gB.a1 = in_v[vB.r01];
    gA.b1 = in_v[vA.r01 + 1]; gB.b1 = in_v[vB.r01 + 1];
    gA.a2 = in_v[vA.r10];     gB.a2 = in_v[vB.r10];
    gA.b2 = in_v[vA.r10 + 1]; gB.b2 = in_v[vB.r10 + 1];
    gA.a3 = in_v[vA.r11];     gB.a3 = in_v[vB.r11];
    gA.b3 = in_v[vA.r11 + 1]; gB.b3 = in_v[vB.r11 + 1];

    float a0, a1, a2, b0, b1, b2;
    vx_blend(vA, gA, a0, a1, a2);
    vx_blend(vB, gB, b0, b1, b2);

    if (OUT_PACKED) {
        // Output is never re-read: streaming stores keep L2 for the gathers.
        float* pA = out_p + (size_t)baseA * 3;
        __stcs(pA + 0, a0); __stcs(pA + 1, a1); __stcs(pA + 2, a2);
        float* pB = out_p + (size_t)baseB * 3;
        __stcs(pB + 0, b0); __stcs(pB + 1, b1); __stcs(pB + 2, b2);
    } else {
        out_v[baseA] = f3_to_h4(a0, a1, a2);
        out_v[baseB] = f3_to_h4(b0, b1, b2);
    }
}

extern "C" void kernel_launch(void* const* d_in, const int* in_sizes, int n_in,
                              void* d_out, int out_size)
{
    (void)in_sizes; (void)n_in; (void)out_size;
    const float4* vel = (const float4*)d_in[0];
    float*        out = (float*)d_out;

    uint2 *A = nullptr, *B = nullptr;
    cudaGetSymbolAddress((void**)&A, g_bufA);
    cudaGetSymbolAddress((void**)&B, g_bufB);

    vecint_convert<<<NVOX / 4 / 256, 256>>>(vel, (uint4*)A);

    const dim3 blk(32, 4, 2);                               // 256 threads
    const dim3 grd(DIMS / 32, DIMS / 4, (DIMS / 4) * NB);   // 2 voxels/thread

    vecint_step<false><<<grd, blk>>>(A, nullptr, B);   // 1
    vecint_step<false><<<grd, blk>>>(B, nullptr, A);   // 2
    vecint_step<false><<<grd, blk>>>(A, nullptr, B);   // 3
    vecint_step<false><<<grd, blk>>>(B, nullptr, A);   // 4
    vecint_step<false><<<grd, blk>>>(A, nullptr, B);   // 5
    vecint_step<false><<<grd, blk>>>(B, nullptr, A);   // 6
    vecint_step<true ><<<grd, blk>>>(A, out, nullptr); // 7
}

// round 17
// speedup vs baseline: 1.0484x; 1.0266x over previous
#include <cuda_runtime.h>
#include <cuda_fp16.h>

// VecInt: 7-step scaling-and-squaring integration of [2,128,128,128,3] f32.
//   v0 = vel/128;  v <- v + trilinear_warp(v, v)  x7
//
// R17 = R11 kernels (fp16x4 voxels, single-copy ping-pong, adjacent-d voxel
// pair per thread, interleaved front-loaded 2x9 LDG.64 burst, __ldcs/__stcs
// hints; 32 regs, ~83% occ) + PDL (programmatic dependent launch) across all
// 8 kernels: each pass triggers griddepcontrol.launch_dependents at CTA start
// (grid-wide fire ~ start of the last wave) and dependents run their prologue
// then griddepcontrol.wait before the first dependent load — overlapping
// launch latency and tail-wave drain between passes. Memory visibility at
// .wait is full, so results are bit-identical (rel_err 4.6838e-4).

static constexpr int DIMS = 128;
static constexpr int NB   = 2;
static constexpr int NVOX = NB * DIMS * DIMS * DIMS;
static constexpr int DSTRIDE = DIMS * DIMS;           // 16384

#define GDC_LAUNCH() asm volatile("griddepcontrol.launch_dependents;")
#define GDC_WAIT()   asm volatile("griddepcontrol.wait;" ::: "memory")

// +2 pad: zero-weighted stray read at iw0==127 lands here (zero-init'd).
__device__ __align__(16) uint2 g_bufA[NVOX + 2];
__device__ __align__(16) uint2 g_bufB[NVOX + 2];

__device__ __forceinline__ void h4_to_f3(uint2 u, float& x, float& y, float& z)
{
    __half2 h01 = *reinterpret_cast<__half2*>(&u.x);
    __half2 h23 = *reinterpret_cast<__half2*>(&u.y);
    float2  f01 = __half22float2(h01);
    x = f01.x; y = f01.y; z = __low2float(h23);
}

__device__ __forceinline__ uint2 f3_to_h4(float x, float y, float z)
{
    __half2 h01 = __floats2half2_rn(x, y);
    __half2 h23 = __floats2half2_rn(z, 0.0f);
    uint2 u;
    u.x = *reinterpret_cast<unsigned int*>(&h01);
    u.y = *reinterpret_cast<unsigned int*>(&h23);
    return u;
}

// ---------- pass 0: packed f32x3 -> fp16x4, folding 1/128 -------------------
__global__ __launch_bounds__(256)
void vecint_convert(const float4* __restrict__ in, uint4* __restrict__ out)
{
    GDC_LAUNCH();                              // let pass 1 spin up early
    const int t = blockIdx.x * blockDim.x + threadIdx.x;
    const float s = 1.0f / 128.0f;
    const float4 a = __ldcs(in + 3 * t + 0);   // read-once: evict-first
    const float4 b = __ldcs(in + 3 * t + 1);
    const float4 c = __ldcs(in + 3 * t + 2);
    const uint2 v0 = f3_to_h4(a.x * s, a.y * s, a.z * s);
    const uint2 v1 = f3_to_h4(a.w * s, b.x * s, b.y * s);
    const uint2 v2 = f3_to_h4(b.z * s, b.w * s, c.x * s);
    const uint2 v3 = f3_to_h4(c.y * s, c.z * s, c.w * s);
    out[2 * t + 0] = make_uint4(v0.x, v0.y, v1.x, v1.y);
    out[2 * t + 1] = make_uint4(v2.x, v2.y, v3.x, v3.y);
}

// ---------- per-voxel machinery ---------------------------------------------
struct Vx {
    int   r00, r01, r10, r11;
    float f0, f1, f2, w00, w01, w10, w11, ww0, ww1;
};

__device__ __forceinline__ Vx vx_setup(uint2 own, int b, float df, float hf,
                                       float wf)
{
    Vx v;
    h4_to_f3(own, v.f0, v.f1, v.f2);

    const float ldc = fminf(fmaxf(df + v.f0, 0.0f), 127.0f);
    const float lhc = fminf(fmaxf(hf + v.f1, 0.0f), 127.0f);
    const float lwc = fminf(fmaxf(wf + v.f2, 0.0f), 127.0f);

    const float fd = floorf(ldc), fh = floorf(lhc), fw = floorf(lwc);
    const int   id0 = (int)fd,  ih0 = (int)fh,  iw0 = (int)fw;
    const float wd1 = ldc - fd, wh1 = lhc - fh;
    const float wd0 = 1.0f - wd1, wh0 = 1.0f - wh1;
    v.ww1 = lwc - fw; v.ww0 = 1.0f - v.ww1;

    const int dd = (id0 < 127) ? DSTRIDE : 0;
    const int dh = (ih0 < 127) ? DIMS : 0;
    v.r00 = ((b * DIMS + id0) * DIMS + ih0) * DIMS + iw0;
    v.r01 = v.r00 + dh;
    v.r10 = v.r00 + dd;
    v.r11 = v.r10 + dh;

    v.w00 = wd0 * wh0; v.w01 = wd0 * wh1;
    v.w10 = wd1 * wh0; v.w11 = wd1 * wh1;
    return v;
}

struct Gather { uint2 a0, b0, a1, b1, a2, b2, a3, b3; };

__device__ __forceinline__ void vx_blend(const Vx& v, const Gather& g,
                                         float& o0, float& o1, float& o2)
{
    float r0 = 0.0f, r1 = 0.0f, r2 = 0.0f;
    float x0, y0, z0, x1, y1, z1;
#define BLEND(A, B, WDH)                                                  \
    h4_to_f3(A, x0, y0, z0); h4_to_f3(B, x1, y1, z1);                     \
    {   const float g0 = (WDH) * v.ww0, g1 = (WDH) * v.ww1;               \
        r0 = fmaf(g0, x0, fmaf(g1, x1, r0));                              \
        r1 = fmaf(g0, y0, fmaf(g1, y1, r1));                              \
        r2 = fmaf(g0, z0, fmaf(g1, z1, r2)); }
    BLEND(g.a0, g.b0, v.w00)
    BLEND(g.a1, g.b1, v.w01)
    BLEND(g.a2, g.b2, v.w10)
    BLEND(g.a3, g.b3, v.w11)
#undef BLEND
    o0 = v.f0 + r0; o1 = v.f1 + r1; o2 = v.f2 + r2;
}

// ---------- integration step: adjacent-d voxel pair per thread --------------
template<bool OUT_PACKED>
__global__ __launch_bounds__(256)
void vecint_step(const uint2* __restrict__ in_v,
                 float*       __restrict__ out_p,
                 uint2*       __restrict__ out_v)
{
    GDC_LAUNCH();                 // grid-wide fire ~ start of last wave

    // Prologue (overlappable with the previous pass's tail).
    const int w  = blockIdx.x * 32 + threadIdx.x;
    const int h  = blockIdx.y * 4  + threadIdx.y;
    const int zb = blockIdx.z;                  // 64: 32 d-quads x 2 batches
    const int b  = zb >> 5;
    const int d  = ((zb & 31) << 2) + (threadIdx.z << 1);  // pair: d, d+1

    const int baseA = ((b * DIMS + d) * DIMS + h) * DIMS + w;
    const int baseB = baseA + DSTRIDE;
    const float hf = (float)h, wf = (float)w, df = (float)d;

    GDC_WAIT();                   // previous pass complete + memory visible

    // Own-voxel loads first (both in flight).
    const uint2 ownA = in_v[baseA];
    const uint2 ownB = in_v[baseB];

    const Vx vA = vx_setup(ownA, b, df,        hf, wf);
    const Vx vB = vx_setup(ownB, b, df + 1.0f, hf, wf);

    // Interleaved front-loaded gather bursts (~16 loads in flight).
    Gather gA, gB;
    gA.a0 = in_v[vA.r00];     gB.a0 = in_v[vB.r00];
    gA.b0 = in_v[vA.r00 + 1]; gB.b0 = in_v[vB.r00 + 1];
    gA.a1 = in_v[vA.r01];     gB.a1 = in_v[vB.r01];
    gA.b1 = in_v[vA.r01 + 1]; gB.b1 = in_v[vB.r01 + 1];
    gA.a2 = in_v[vA.r10];     gB.a2 = in_v[vB.r10];
    gA.b2 = in_v[vA.r10 + 1]; gB.b2 = in_v[vB.r10 + 1];
    gA.a3 = in_v[vA.r11];     gB.a3 = in_v[vB.r11];
    gA.b3 = in_v[vA.r11 + 1]; gB.b3 = in_v[vB.r11 + 1];

    float a0, a1, a2, b0, b1, b2;
    vx_blend(vA, gA, a0, a1, a2);
    vx_blend(vB, gB, b0, b1, b2);

    if (OUT_PACKED) {
        // Output is never re-read: streaming stores keep L2 for the gathers.
        float* pA = out_p + (size_t)baseA * 3;
        __stcs(pA + 0, a0); __stcs(pA + 1, a1); __stcs(pA + 2, a2);
        float* pB = out_p + (size_t)baseB * 3;
        __stcs(pB + 0, b0); __stcs(pB + 1, b1); __stcs(pB + 2, b2);
    } else {
        out_v[baseA] = f3_to_h4(a0, a1, a2);
        out_v[baseB] = f3_to_h4(b0, b1, b2);
    }
}

extern "C" void kernel_launch(void* const* d_in, const int* in_sizes, int n_in,
                              void* d_out, int out_size)
{
    (void)in_sizes; (void)n_in; (void)out_size;
    const float4* vel = (const float4*)d_in[0];
    float*        out = (float*)d_out;

    uint2 *A = nullptr, *B = nullptr;
    cudaGetSymbolAddress((void**)&A, g_bufA);
    cudaGetSymbolAddress((void**)&B, g_bufB);

    // PDL attribute shared by all launches (stream 0 = capture stream).
    cudaLaunchAttribute attr[1];
    attr[0].id = cudaLaunchAttributeProgrammaticStreamSerialization;
    attr[0].val.programmaticStreamSerializationAllowed = 1;

    cudaLaunchConfig_t cvt = {};
    cvt.gridDim  = dim3(NVOX / 4 / 256, 1, 1);
    cvt.blockDim = dim3(256, 1, 1);
    cvt.stream   = 0;
    cvt.attrs    = attr;
    cvt.numAttrs = 1;
    cudaLaunchKernelEx(&cvt, vecint_convert, vel, (uint4*)A);

    cudaLaunchConfig_t stp = {};
    stp.gridDim  = dim3(DIMS / 32, DIMS / 4, (DIMS / 4) * NB);
    stp.blockDim = dim3(32, 4, 2);
    stp.stream   = 0;
    stp.attrs    = attr;
    stp.numAttrs = 1;

    float* nofp = nullptr;
    uint2* nov  = nullptr;
    cudaLaunchKernelEx(&stp, vecint_step<false>, (const uint2*)A, nofp, B); // 1
    cudaLaunchKernelEx(&stp, vecint_step<false>, (const uint2*)B, nofp, A); // 2
    cudaLaunchKernelEx(&stp, vecint_step<false>, (const uint2*)A, nofp, B); // 3
    cudaLaunchKernelEx(&stp, vecint_step<false>, (const uint2*)B, nofp, A); // 4
    cudaLaunchKernelEx(&stp, vecint_step<false>, (const uint2*)A, nofp, B); // 5
    cudaLaunchKernelEx(&stp, vecint_step<false>, (const uint2*)B, nofp, A); // 6
    cudaLaunchKernelEx(&stp, vecint_step<true>,  (const uint2*)A, out, nov); // 7
}